// round 9
// baseline (speedup 1.0000x reference)
#include <cuda_runtime.h>
#include <cstdint>

#define BB 16
#define HH 1024
#define WW 1024
#define WORDS 32                    // uint32 words per row
#define HW (HH * WW)
#define NPIX (BB * HW)
#define NWORDS (BB * HH * WORDS)

#define NBLK 592                    // 148 SMs x 4 blocks, co-resident
#define NTHR 256
#define NTHREADS (NBLK * NTHR)
#define NWARPS (NTHREADS / 32)

#define ITROWS 4                    // rows per work item
#define ITEMS ((BB * HH) / ITROWS)  // 4096 items

__device__ unsigned int g_tbits[NWORDS];   // packed target bits (2 MiB)
__device__ unsigned long long g_ecount;
__device__ double g_A;
__device__ double g_B;
__device__ unsigned g_done;
__device__ unsigned g_c1;
__device__ volatile unsigned g_f1;

__device__ __forceinline__ float ex2f(float x) {
    float r; asm("ex2.approx.f32 %0, %1;" : "=f"(r) : "f"(x)); return r;
}
__device__ __forceinline__ void pf_l2(const void* p) {
    asm volatile("prefetch.global.L2 [%0];" :: "l"(p));
}

// prefetch the 64KB score payload of item `it` (512 lines; 2 per thread)
__device__ __forceinline__ void prefetch_item(const float* s0, const float* s1,
                                              int it, int tid) {
    int pb = it >> 8;
    int pr = (it & 255) * ITROWS;
    size_t pbase = (size_t)pb * 2 * HW + (size_t)pr * WW;
    #pragma unroll
    for (int q = 0; q < 2; q++) {
        int L = tid * 2 + q;                       // 0..511 line id
        const float* bp = (L & 256) ? s1 : s0;
        size_t off = pbase + ((L & 128) ? HW : 0)
                   + (size_t)((L >> 5) & 3) * WW + (L & 31) * 32;
        pf_l2(bp + off);
    }
}

__global__ void __launch_bounds__(NTHR, 4)
k_fused(const float* __restrict__ s0, const float* __restrict__ s1,
        const int* __restrict__ tgt, float* __restrict__ out) {
    __shared__ unsigned se[ITROWS * WORDS];  // edge bits for current item
    __shared__ float sA[NTHR];
    __shared__ float sB[NTHR];
    __shared__ unsigned s_cnt;

    const int tid   = threadIdx.x;
    const int lane  = tid & 31;
    const int gwarp = (blockIdx.x * NTHR + tid) >> 5;

    if (tid == 0) s_cnt = 0;

    // warm L2 with this block's first item while pack runs
    prefetch_item(s0, s1, blockIdx.x, tid);

    // ---------- Phase 1: pack target bits (grid-strided, balanced) ---------
    for (int w = gwarp; w < NPIX / 128; w += NWARPS) {
        int base = w * 128;
        int t0 = tgt[base + lane];
        int t1 = tgt[base + 32 + lane];
        int t2 = tgt[base + 64 + lane];
        int t3 = tgt[base + 96 + lane];
        unsigned b0 = __ballot_sync(0xffffffffu, t0 != 0);
        unsigned b1 = __ballot_sync(0xffffffffu, t1 != 0);
        unsigned b2 = __ballot_sync(0xffffffffu, t2 != 0);
        unsigned b3 = __ballot_sync(0xffffffffu, t3 != 0);
        if (lane == 0)
            *(uint4*)&g_tbits[w * 4] = make_uint4(b0, b1, b2, b3);
    }

    // ---------- Grid barrier -----------------------------------------------
    __syncthreads();
    if (tid == 0) {
        __threadfence();
        if (atomicAdd(&g_c1, 1u) == NBLK - 1) g_f1 = 1u;
        else while (g_f1 == 0u) __nanosleep(32);
        __threadfence();
    }
    __syncthreads();

    // ---------- Phase 2: items of 4 rows, statically strided ---------------
    float accA = 0.f, accB = 0.f;
    unsigned ecnt = 0;
    const float LOG2E = 1.4426950408889634f;

    const int rsub = tid >> 7;               // row within pair (0/1)
    const int c8   = (tid & 127) * 8;        // 8-px column
    const int wj8  = c8 >> 5;
    const int sh8  = c8 & 31;

    for (int it = blockIdx.x; it < ITEMS; it += NBLK) {
        int bimg = it >> 8;                  // item / (HH/ITROWS)
        int r0   = (it & 255) * ITROWS;
        int wbase = (bimg * HH + r0) * WORDS;

        // keep DRAM streaming: pull next item's lines into L2 now
        int nit = it + NBLK;
        prefetch_item(s0, s1, nit < ITEMS ? nit : it, tid);

        __syncthreads();                     // protect se from prior readers

        // ---- edge words: 128 threads, one word each (4 rows x 32 words) ---
        if (tid < ITROWS * WORDS) {
            int rl = tid >> 5, j = tid & 31;
            int gr0 = r0 + rl;
            unsigned orL = 0, orM = 0, orR = 0;
            unsigned anL = ~0u, anM = ~0u, anR = ~0u;
            unsigned T = 0;
            #pragma unroll
            for (int d = 0; d < 11; ++d) {
                int gr = gr0 + d - 5;
                unsigned wl = 0, wm = 0, wr = 0;
                if ((unsigned)gr < HH) {
                    const unsigned* p = g_tbits + (bimg * HH + gr) * WORDS;
                    wm = p[j];
                    wl = (j > 0)  ? p[j - 1] : 0u;
                    wr = (j < 31) ? p[j + 1] : 0u;
                }
                if (d == 5) T = wm;
                orL |= wl; orM |= wm; orR |= wr;
                anL &= wl; anM &= wm; anR &= wr;
            }
            unsigned nL = ~anL, nM = ~anM, nR = ~anR;
            unsigned any1 = orM, any0 = nM;
            #pragma unroll
            for (int s = 1; s <= 5; s++) {
                any1 |= __funnelshift_r(orM, orR, s);
                any1 |= __funnelshift_l(orL, orM, s);
                any0 |= __funnelshift_r(nM, nR, s);
                any0 |= __funnelshift_l(nL, nM, s);
            }
            unsigned e = (T & any0) | (~T & any1);
            se[tid] = e;
            ecnt += __popc(e);
        }
        __syncthreads();

        // ---- bits for this thread's two rows (shared by both tensors) -----
        unsigned tw0 = g_tbits[wbase + rsub * WORDS + wj8] >> sh8;
        unsigned ew0 = se[rsub * WORDS + wj8] >> sh8;
        unsigned tw1 = g_tbits[wbase + (rsub + 2) * WORDS + wj8] >> sh8;
        unsigned ew1 = se[(rsub + 2) * WORDS + wj8] >> sh8;
        unsigned ntw0 = ~tw0, ntw1 = ~tw1;

        size_t pixbase = (size_t)bimg * 2 * HW + (size_t)(r0 + rsub) * WW + c8;

        // ---- per-tensor sub-blocks: 8 batched float4 each, weight w -------
        #pragma unroll 1
        for (int t = 0; t < 2; t++) {
            const float w = t ? 0.5f : 1.0f;
            const float* b0 = (t ? s1 : s0) + pixbase;   // class-0 plane
            const float* b1 = b0 + HW;                    // class-1 plane

            float4 a0  = *(const float4*)(b0);
            float4 a0b = *(const float4*)(b0 + 4);
            float4 a1  = *(const float4*)(b1);
            float4 a1b = *(const float4*)(b1 + 4);
            float4 d0  = *(const float4*)(b0 + 2 * WW);
            float4 d0b = *(const float4*)(b0 + 2 * WW + 4);
            float4 d1  = *(const float4*)(b1 + 2 * WW);
            float4 d1b = *(const float4*)(b1 + 2 * WW + 4);

            float x0[8] = {a0.x, a0.y, a0.z, a0.w, a0b.x, a0b.y, a0b.z, a0b.w};
            float x1[8] = {a1.x, a1.y, a1.z, a1.w, a1b.x, a1b.y, a1b.z, a1b.w};
            #pragma unroll
            for (int k = 0; k < 8; k++) {
                unsigned sflip = (ntw0 << (31 - k)) & 0x80000000u;
                int      emask = ((int)(ew0 << (31 - k))) >> 31;
                float dd = (x1[k] - x0[k]) * LOG2E;
                float u  = __int_as_float(__float_as_int(dd) ^ sflip);
                float z  = ex2f(-fabsf(u));
                float sp = fmaxf(-u, 0.f) + __log2f(1.f + z);
                accA += w * sp;
                float Bt = w * (0.5f * sp + u);
                accB += __int_as_float(__float_as_int(Bt) & emask);
            }

            float y0[8] = {d0.x, d0.y, d0.z, d0.w, d0b.x, d0b.y, d0b.z, d0b.w};
            float y1[8] = {d1.x, d1.y, d1.z, d1.w, d1b.x, d1b.y, d1b.z, d1b.w};
            #pragma unroll
            for (int k = 0; k < 8; k++) {
                unsigned sflip = (ntw1 << (31 - k)) & 0x80000000u;
                int      emask = ((int)(ew1 << (31 - k))) >> 31;
                float dd = (y1[k] - y0[k]) * LOG2E;
                float u  = __int_as_float(__float_as_int(dd) ^ sflip);
                float z  = ex2f(-fabsf(u));
                float sp = fmaxf(-u, 0.f) + __log2f(1.f + z);
                accA += w * sp;
                float Bt = w * (0.5f * sp + u);
                accB += __int_as_float(__float_as_int(Bt) & emask);
            }
        }
    }

    // ---------- Block reduction + global accumulation ----------------------
    ecnt = __reduce_add_sync(0xffffffffu, ecnt);
    if (lane == 0 && ecnt) atomicAdd(&s_cnt, ecnt);

    sA[tid] = accA;
    sB[tid] = accB;
    __syncthreads();
    #pragma unroll
    for (int s = NTHR / 2; s > 0; s >>= 1) {
        if (tid < s) { sA[tid] += sA[tid + s]; sB[tid] += sB[tid + s]; }
        __syncthreads();
    }

    if (tid == 0) {
        atomicAdd(&g_A, (double)sA[0]);
        atomicAdd(&g_B, (double)sB[0]);
        atomicAdd(&g_ecount, (unsigned long long)s_cnt);
        __threadfence();
        unsigned done = atomicAdd(&g_done, 1u);
        if (done == NBLK - 1) {
            const double LN2 = 0.6931471805599453;
            double N = (double)NPIX;
            double a = (double)g_ecount / N;
            if (a > 0.2) a = 0.2;
            out[0] = (float)((g_A + a * g_B) * LN2 / N);
            // reset ALL state for the next graph replay
            g_A = 0.0; g_B = 0.0; g_ecount = 0ull;
            g_c1 = 0u; g_f1 = 0u;
            __threadfence();
            g_done = 0u;
        }
    }
}

// ---------------------------------------------------------------------------
extern "C" void kernel_launch(void* const* d_in, const int* in_sizes, int n_in,
                              void* d_out, int out_size) {
    int ti = 0;
    for (int i = 1; i < n_in; i++)
        if (in_sizes[i] < in_sizes[ti]) ti = i;
    const float* s0 = nullptr;
    const float* s1 = nullptr;
    for (int i = 0; i < n_in; i++) {
        if (i == ti) continue;
        if (!s0) s0 = (const float*)d_in[i];
        else     s1 = (const float*)d_in[i];
    }
    const int* tgt = (const int*)d_in[ti];

    k_fused<<<NBLK, NTHR>>>(s0, s1, tgt, (float*)d_out);
}